// round 5
// baseline (speedup 1.0000x reference)
#include <cuda_runtime.h>
#include <cstdint>

#define BATCH 64
#define NSEQ  2048
#define CDIM  128
#define HP    64
#define WP    32
#define HG    32   // HP / POOL
#define D_SCALE 0.08838834764831845f  // 1/sqrt(128)

// Scratch: Q,K,V in [B, C, N] (spatial-major) layout. V plane is overwritten
// with the attention output by attn_kernel (each CTA exclusively owns its plane,
// and proj writes it fully on every graph replay -> deterministic).
__device__ float g_QT[(size_t)BATCH * CDIM * NSEQ];
__device__ float g_KT[(size_t)BATCH * CDIM * NSEQ];
__device__ float g_VT[(size_t)BATCH * CDIM * NSEQ];

// Precomputed W fragments: [p][ntg*8+ks][lane] -> uint4 (b0_hi, b1_hi, b0_lo, b1_lo)
__device__ uint4 g_Wpk[3 * 4096];

// A-fragment smem addressing: per (mt, ks) block of 32 lanes, stride 33 uint4s
// (pad kills staging bank conflicts; mainloop reads stay dense per 32-lane block).
#define APOS(mt, ks) (((mt) * 8 + (ks)) * 33)

// Pack two fp32 into bf16x2: e0 -> low 16 bits (even k), e1 -> high (odd k).
__device__ __forceinline__ uint32_t bf16x2_of(float e0, float e1) {
    uint32_t r;
    asm("cvt.rn.bf16x2.f32 %0, %1, %2;" : "=r"(r) : "f"(e1), "f"(e0));
    return r;
}
__device__ __forceinline__ float lo_f(uint32_t p) { return __uint_as_float(p << 16); }
__device__ __forceinline__ float hi_f(uint32_t p) { return __uint_as_float(p & 0xffff0000u); }

__device__ __forceinline__ void mma_bf16(float* d,
                                         uint32_t a0, uint32_t a1, uint32_t a2, uint32_t a3,
                                         uint32_t b0, uint32_t b1) {
    asm volatile(
        "mma.sync.aligned.m16n8k16.row.col.f32.bf16.bf16.f32 "
        "{%0,%1,%2,%3}, {%4,%5,%6,%7}, {%8,%9}, {%0,%1,%2,%3};"
        : "+f"(d[0]), "+f"(d[1]), "+f"(d[2]), "+f"(d[3])
        : "r"(a0), "r"(a1), "r"(a2), "r"(a3), "r"(b0), "r"(b1));
}

// ---------------------------------------------------------------------------
// Kernel 0: convert W matrices into MMA-fragment-packed bf16 hi/lo, once.
// pos = (ntg*8 + ks)*32 + lane; lane = gj*4 + s; j = ntg*8+gj;
// word x = hi(k=2s,2s+1), y = hi(k=2s+8,2s+9), z/w = residual lo of x/y.
// ---------------------------------------------------------------------------
__global__ __launch_bounds__(256) void prep_w_kernel(
    const float* __restrict__ Wq, const float* __restrict__ Wk,
    const float* __restrict__ Wv)
{
    const int p = blockIdx.x;
    const float* W = (p == 0) ? Wq : (p == 1) ? Wk : Wv;
    const int t = threadIdx.x;
    #pragma unroll
    for (int i = 0; i < 16; ++i) {
        const int pos  = t + i * 256;        // 0..4095
        const int lane = pos & 31;
        const int ks   = (pos >> 5) & 7;
        const int ntg  = pos >> 8;
        const int gj   = lane >> 2;
        const int s    = lane & 3;
        const int j    = ntg * 8 + gj;
        const int c0   = ks * 16 + 2 * s;
        const float w0 = W[j * CDIM + c0],     w1 = W[j * CDIM + c0 + 1];
        const float w2 = W[j * CDIM + c0 + 8], w3 = W[j * CDIM + c0 + 9];
        uint32_t x = bf16x2_of(w0, w1);
        uint32_t y = bf16x2_of(w2, w3);
        uint32_t z = bf16x2_of(w0 - lo_f(x), w1 - hi_f(x));
        uint32_t w = bf16x2_of(w2 - lo_f(y), w3 - hi_f(y));
        g_Wpk[p * 4096 + pos] = make_uint4(x, y, z, w);
    }
}

// ---------------------------------------------------------------------------
// Kernel 1: projection GEMMs, 3-term bf16 split (hi*hi + lo*hi + hi*lo).
// M-tile = 256 rows. 512 threads = 16 warps: warp = (mgroup 0..7) x (nhalf 0..1),
// warp computes 32 m-rows (2 m16 tiles) x 64 j (8 n8 tiles): each W LDS.128
// feeds 6 MMAs. A staged ONCE as packed bf16 hi/lo fragments; W fragments
// copied from precomputed global. Epilogue transposes half-tiles through the
// retired Wb region. Out = sigmoid(X@W^T + b) stored OutT[b][j][n].
// ---------------------------------------------------------------------------
__global__ __launch_bounds__(512) void proj_mma_kernel(
    const float* __restrict__ X,
    const float* __restrict__ bq, const float* __restrict__ bk,
    const float* __restrict__ bv)
{
    extern __shared__ float sm[];
    uint4* Ahi = (uint4*)sm;           // 16*8*33 = 4224 uint4 (67.6 KB)
    uint4* Alo = Ahi + 4224;           // 4224 uint4 (67.6 KB)
    uint4* Wb  = Alo + 4224;           // 4096 uint4 used; region sized 4224 for T
    float* T   = (float*)Wb;           // [128 j][132] transpose buffer (aliases Wb)

    const int t    = threadIdx.x;
    const int warp = t >> 5;
    const int lane = t & 31;
    const int M0   = blockIdx.x * 256;
    const int bidx = M0 >> 11;          // batch index (256 | 2048)
    const int n0   = M0 & 2047;

    const int g    = lane >> 2;   // 0..7
    const int tid  = lane & 3;    // 0..3
    const int mgroup = warp & 7;
    const int nhalf  = warp >> 3;
    const int mt0 = mgroup * 2, mt1 = mt0 + 1;

    // ---- Stage A: X[M0..M0+255][0..127] -> packed bf16 hi/lo fragments ----
    {
        const int r  = t >> 5;          // 0..15
        const int c4 = (t & 31) << 2;   // 0..124
        const int ks = c4 >> 4;
        const int kk = c4 & 15;
        const int t0 = (kk & 7) >> 1;               // 0 or 2
        const int wb = ((kk >= 8) ? 2 : 0) + ((r >= 8) ? 1 : 0);
        const int gr = r & 7;
        #pragma unroll
        for (int it = 0; it < 16; ++it) {
            const int row = it * 16 + r;            // 0..255, mt = it
            float4 xv = *(const float4*)(X + (size_t)(M0 + row) * CDIM + c4);
            uint32_t hiA = bf16x2_of(xv.x, xv.y);
            uint32_t hiB = bf16x2_of(xv.z, xv.w);
            uint32_t loA = bf16x2_of(xv.x - lo_f(hiA), xv.y - hi_f(hiA));
            uint32_t loB = bf16x2_of(xv.z - lo_f(hiB), xv.w - hi_f(hiB));
            uint32_t* dh = (uint32_t*)(Ahi + APOS(it, ks) + gr * 4 + t0);
            uint32_t* dl = (uint32_t*)(Alo + APOS(it, ks) + gr * 4 + t0);
            dh[wb]     = hiA;
            dh[4 + wb] = hiB;
            dl[wb]     = loA;
            dl[4 + wb] = loB;
        }
    }

    // ---- Copy W fragments for p=0 (independent of A staging) ----
    #pragma unroll
    for (int i = 0; i < 8; ++i)
        Wb[t + i * 512] = g_Wpk[t + i * 512];
    __syncthreads();

    #pragma unroll 1
    for (int p = 0; p < 3; ++p) {
        const float* bias = (p == 0) ? bq : (p == 1) ? bk : bv;
        float* OutT       = (p == 0) ? g_QT : (p == 1) ? g_KT : g_VT;

        // ---- MMA mainloop ----
        float acc[2][8][4];
        #pragma unroll
        for (int mi = 0; mi < 2; ++mi)
            #pragma unroll
            for (int nt = 0; nt < 8; ++nt)
                #pragma unroll
                for (int q = 0; q < 4; ++q) acc[mi][nt][q] = 0.0f;

        #pragma unroll
        for (int ks = 0; ks < 8; ++ks) {
            uint4 ah0 = Ahi[APOS(mt0, ks) + lane];
            uint4 al0 = Alo[APOS(mt0, ks) + lane];
            uint4 ah1 = Ahi[APOS(mt1, ks) + lane];
            uint4 al1 = Alo[APOS(mt1, ks) + lane];
            #pragma unroll
            for (int nt = 0; nt < 8; ++nt) {
                uint4 w = Wb[((nhalf * 8 + nt) * 8 + ks) * 32 + lane];
                mma_bf16(acc[0][nt], ah0.x, ah0.y, ah0.z, ah0.w, w.x, w.y);
                mma_bf16(acc[0][nt], al0.x, al0.y, al0.z, al0.w, w.x, w.y);
                mma_bf16(acc[0][nt], ah0.x, ah0.y, ah0.z, ah0.w, w.z, w.w);
                mma_bf16(acc[1][nt], ah1.x, ah1.y, ah1.z, ah1.w, w.x, w.y);
                mma_bf16(acc[1][nt], al1.x, al1.y, al1.z, al1.w, w.x, w.y);
                mma_bf16(acc[1][nt], ah1.x, ah1.y, ah1.z, ah1.w, w.z, w.w);
            }
        }

        // ---- Epilogue: two m-halves of 128 transposed through T (=Wb) ----
        #pragma unroll 1
        for (int half = 0; half < 2; ++half) {
            __syncthreads();   // Wb reads done (h0) / prev STG done (h1)
            if ((mgroup >> 2) == half) {
                #pragma unroll
                for (int mi = 0; mi < 2; ++mi) {
                    const int mloc = (mgroup & 3) * 32 + mi * 16 + g;
                    #pragma unroll
                    for (int nt = 0; nt < 8; ++nt) {
                        const int j0 = (nhalf * 8 + nt) * 8 + 2 * tid;
                        const float b0v = __ldg(bias + j0);
                        const float b1v = __ldg(bias + j0 + 1);
                        float v0 = acc[mi][nt][0] + b0v;
                        float v1 = acc[mi][nt][1] + b1v;
                        float v2 = acc[mi][nt][2] + b0v;
                        float v3 = acc[mi][nt][3] + b1v;
                        v0 = 1.0f / (1.0f + __expf(-v0));
                        v1 = 1.0f / (1.0f + __expf(-v1));
                        v2 = 1.0f / (1.0f + __expf(-v2));
                        v3 = 1.0f / (1.0f + __expf(-v3));
                        T[j0 * 132 + mloc]           = v0;
                        T[(j0 + 1) * 132 + mloc]     = v1;
                        T[j0 * 132 + mloc + 8]       = v2;
                        T[(j0 + 1) * 132 + mloc + 8] = v3;
                    }
                }
            }
            __syncthreads();
            #pragma unroll
            for (int it = 0; it < 8; ++it) {
                const int idx = t + it * 512;     // 0..4095
                const int j   = idx >> 5;
                const int m4  = (idx & 31) << 2;
                float4 v = *(const float4*)(T + j * 132 + m4);
                *(float4*)(OutT + ((size_t)bidx * CDIM + j) * NSEQ +
                           n0 + half * 128 + m4) = v;
            }
        }

        // ---- Copy W fragments for next p (T reads done after barrier) ----
        __syncthreads();
        if (p < 2) {
            #pragma unroll
            for (int i = 0; i < 8; ++i)
                Wb[t + i * 512] = g_Wpk[(p + 1) * 4096 + t + i * 512];
            __syncthreads();
        }
    }
}

// ---------------------------------------------------------------------------
// Kernel 2: per-(b,c) dual-softmax attention on a [64,32] plane.
// ---------------------------------------------------------------------------
__global__ __launch_bounds__(256) void attn_kernel()
{
    const int bc = blockIdx.x;                      // b*128 + c
    const float* Qp = g_QT + (size_t)bc * NSEQ;
    const float* Kp = g_KT + (size_t)bc * NSEQ;
    const float* Vp = g_VT + (size_t)bc * NSEQ;
    float* Op = g_VT + (size_t)bc * NSEQ;           // overwrite V plane

    __shared__ float Qs[HP * WP];     // [h][w]
    __shared__ float Vs[HP * WP];     // [h][w]
    __shared__ float KTs[WP * 65];    // [w][h], padded
    __shared__ float kTs[WP * 33];    // [w][g], pooled K, padded
    __shared__ float qs[HG * WP];     // [g][w], pooled Q
    __shared__ float Kqvs[HG * WP];   // [g][w]
    __shared__ float buf[8][264];     // per-warp softmax rows

    const int t    = threadIdx.x;
    const int warp = t >> 5;
    const int lane = t & 31;

    #pragma unroll
    for (int i = 0; i < 2; ++i) {
        int idx = (t + i * 256) * 4;
        float4 qv = *(const float4*)(Qp + idx);
        float4 vv = *(const float4*)(Vp + idx);
        float4 kv = *(const float4*)(Kp + idx);
        *(float4*)(Qs + idx) = qv;
        *(float4*)(Vs + idx) = vv;
        int h = idx >> 5, w = idx & 31;
        KTs[(w + 0) * 65 + h] = kv.x;
        KTs[(w + 1) * 65 + h] = kv.y;
        KTs[(w + 2) * 65 + h] = kv.z;
        KTs[(w + 3) * 65 + h] = kv.w;
    }
    __syncthreads();

    #pragma unroll
    for (int i = 0; i < 4; ++i) {
        int idx = t + i * 256;
        int g = idx >> 5, w = idx & 31;
        qs[g * 32 + w]  = 0.5f * (Qs[(2 * g) * 32 + w] + Qs[(2 * g + 1) * 32 + w]);
        kTs[w * 33 + g] = 0.5f * (KTs[w * 65 + 2 * g] + KTs[w * 65 + 2 * g + 1]);
    }
    __syncthreads();

    // ---- Kq = softmax_h(scale * q @ K^T), Kqv = Kq @ V ----
    {
        const int g0 = warp * 4;
        float s0[4] = {0, 0, 0, 0}, s1[4] = {0, 0, 0, 0};
        #pragma unroll
        for (int w = 0; w < 32; ++w) {
            float k0 = KTs[w * 65 + lane];
            float k1 = KTs[w * 65 + 32 + lane];
            #pragma unroll
            for (int gi = 0; gi < 4; ++gi) {
                float qv = qs[(g0 + gi) * 32 + w];
                s0[gi] = fmaf(qv, k0, s0[gi]);
                s1[gi] = fmaf(qv, k1, s1[gi]);
            }
        }
        #pragma unroll
        for (int gi = 0; gi < 4; ++gi) {
            float a = s0[gi] * D_SCALE, b = s1[gi] * D_SCALE;
            float m = fmaxf(a, b);
            #pragma unroll
            for (int o = 16; o; o >>= 1) m = fmaxf(m, __shfl_xor_sync(0xffffffffu, m, o));
            float e0 = __expf(a - m), e1 = __expf(b - m);
            float sum = e0 + e1;
            #pragma unroll
            for (int o = 16; o; o >>= 1) sum += __shfl_xor_sync(0xffffffffu, sum, o);
            float r = __frcp_rn(sum);
            buf[warp][gi * 66 + lane]      = e0 * r;
            buf[warp][gi * 66 + 32 + lane] = e1 * r;
        }
        __syncwarp();
        const int gi = lane >> 3;
        const int w4 = (lane & 7) << 2;
        float4 acc = {0, 0, 0, 0};
        #pragma unroll 8
        for (int h = 0; h < 64; ++h) {
            float p  = buf[warp][gi * 66 + h];
            float4 v = *(const float4*)(Vs + h * 32 + w4);
            acc.x = fmaf(p, v.x, acc.x);
            acc.y = fmaf(p, v.y, acc.y);
            acc.z = fmaf(p, v.z, acc.z);
            acc.w = fmaf(p, v.w, acc.w);
        }
        *(float4*)(Kqvs + (g0 + gi) * 32 + w4) = acc;
    }
    __syncthreads();

    // ---- Qk = softmax_g(scale * Q @ k^T), out = Qk @ Kqv ----
    {
        const int h0 = warp * 8;
        float s[8] = {0, 0, 0, 0, 0, 0, 0, 0};
        #pragma unroll
        for (int w = 0; w < 32; ++w) {
            float kt = kTs[w * 33 + lane];
            #pragma unroll
            for (int hi = 0; hi < 8; ++hi)
                s[hi] = fmaf(Qs[(h0 + hi) * 32 + w], kt, s[hi]);
        }
        #pragma unroll
        for (int hi = 0; hi < 8; ++hi) {
            float a = s[hi] * D_SCALE;
            float m = a;
            #pragma unroll
            for (int o = 16; o; o >>= 1) m = fmaxf(m, __shfl_xor_sync(0xffffffffu, m, o));
            float e = __expf(a - m);
            float sum = e;
            #pragma unroll
            for (int o = 16; o; o >>= 1) sum += __shfl_xor_sync(0xffffffffu, sum, o);
            buf[warp][hi * 33 + lane] = e * __frcp_rn(sum);
        }
        __syncwarp();
        const int hi = lane >> 2;
        const int w8 = (lane & 3) << 3;
        float4 acc0 = {0, 0, 0, 0}, acc1 = {0, 0, 0, 0};
        #pragma unroll 8
        for (int g = 0; g < 32; ++g) {
            float p   = buf[warp][hi * 33 + g];
            float4 v0 = *(const float4*)(Kqvs + g * 32 + w8);
            float4 v1 = *(const float4*)(Kqvs + g * 32 + w8 + 4);
            acc0.x = fmaf(p, v0.x, acc0.x);
            acc0.y = fmaf(p, v0.y, acc0.y);
            acc0.z = fmaf(p, v0.z, acc0.z);
            acc0.w = fmaf(p, v0.w, acc0.w);
            acc1.x = fmaf(p, v1.x, acc1.x);
            acc1.y = fmaf(p, v1.y, acc1.y);
            acc1.z = fmaf(p, v1.z, acc1.z);
            acc1.w = fmaf(p, v1.w, acc1.w);
        }
        float* dst = Op + (h0 + hi) * 32 + w8;
        *(float4*)(dst)     = acc0;
        *(float4*)(dst + 4) = acc1;
    }
}

// ---------------------------------------------------------------------------
// Kernel 3: [B, C, N] -> [B, N, C] transpose (output epilogue).
// ---------------------------------------------------------------------------
__global__ __launch_bounds__(256) void transpose_kernel(float* __restrict__ out)
{
    __shared__ float tile[32][33];
    const int b  = blockIdx.z;
    const int c0 = blockIdx.y * 32;
    const int n0 = blockIdx.x * 32;
    const int tx = threadIdx.x;
    const int ty = threadIdx.y;

    const float* src = g_VT + (size_t)b * CDIM * NSEQ;
    #pragma unroll
    for (int i = 0; i < 32; i += 8)
        tile[ty + i][tx] = src[(size_t)(c0 + ty + i) * NSEQ + n0 + tx];
    __syncthreads();
    #pragma unroll
    for (int i = 0; i < 32; i += 8)
        out[((size_t)b * NSEQ + n0 + ty + i) * CDIM + c0 + tx] = tile[tx][ty + i];
}

// ---------------------------------------------------------------------------
extern "C" void kernel_launch(void* const* d_in, const int* in_sizes, int n_in,
                              void* d_out, int out_size)
{
    (void)in_sizes; (void)n_in; (void)out_size;
    const float* X  = (const float*)d_in[0];
    const float* Wq = (const float*)d_in[1];
    const float* bq = (const float*)d_in[2];
    const float* Wk = (const float*)d_in[3];
    const float* bk = (const float*)d_in[4];
    const float* Wv = (const float*)d_in[5];
    const float* bv = (const float*)d_in[6];
    float* out = (float*)d_out;

    // Ahi + Alo + Wb/T regions: 3 * 4224 uint4 = 202752 bytes
    const size_t proj_smem = (size_t)3 * 4224 * sizeof(uint4);
    cudaFuncSetAttribute(proj_mma_kernel, cudaFuncAttributeMaxDynamicSharedMemorySize,
                         (int)proj_smem);

    prep_w_kernel<<<dim3(3, 1, 1), 256>>>(Wq, Wk, Wv);
    proj_mma_kernel<<<dim3(512, 1, 1), 512, proj_smem>>>(X, bq, bk, bv);
    attn_kernel<<<dim3(BATCH * CDIM, 1, 1), 256>>>();
    transpose_kernel<<<dim3(NSEQ / 32, CDIM / 32, BATCH), dim3(32, 8, 1)>>>(out);
}